// round 7
// baseline (speedup 1.0000x reference)
#include <cuda_runtime.h>
#include <cuda_bf16.h>
#include <cooperative_groups.h>
#include <cstdint>

namespace cg = cooperative_groups;

// Problem constants (match reference_code)
#define NV       1000000
#define NE       3000000
#define IMG_H    1024
#define IMG_W    1024
#define HW       (IMG_H * IMG_W)       // 1048576
#define MAX_DEPTH 10.0f
#define CREGU    2000.0f

// ---------------- scratch (device globals; zero-initialized at load) --------
__device__ float  g_depth[HW];        // 4 MB    scatter-min target
__device__ float4 g_dv4[NV];          // 16 MB   {dvx, dvy, dvz, 0}
__device__ float4 g_neigh4[NV];       // 16 MB   {nx, ny, nz, deg}
__device__ double g_sums[3];          // vertex component sums (self-zeroing)
__device__ double g_acc;              // total energy accumulator (self-zeroing)

// ---------------- float block reduce (shared) --------------------------------
__device__ __forceinline__ float block_reduce_f(float v) {
    __shared__ float sh[256];
    int t = threadIdx.x;
    sh[t] = v;
    __syncthreads();
    for (int s = blockDim.x >> 1; s > 32; s >>= 1) {
        if (t < s) sh[t] += sh[t + s];
        __syncthreads();
    }
    if (t < 32) {
        float x = sh[t] + sh[t + 32];
        #pragma unroll
        for (int o = 16; o > 0; o >>= 1)
            x += __shfl_down_sync(0xFFFFFFFFu, x, o);
        if (t == 0) sh[0] = x;
    }
    __syncthreads();
    return sh[0];
}

// ---------------- fused cooperative kernel -----------------------------------
__global__ void __launch_bounds__(256)
k_fused(const float4* __restrict__ verts4,
        const float4* __restrict__ vref4,
        const float* __restrict__ quat,
        const float* __restrict__ trans,
        const float4* __restrict__ hand4,
        const float* __restrict__ intr,
        const float* __restrict__ extr,
        const int4* __restrict__ edges2,
        float* __restrict__ out) {
    cg::grid_group grid = cg::this_grid();
    const int tid = blockIdx.x * blockDim.x + threadIdx.x;
    const int nth = gridDim.x * blockDim.x;

    // ===== Phase 1: depth fill + neigh zero + dv + mean partials =====
    {
        float4 md4 = make_float4(MAX_DEPTH, MAX_DEPTH, MAX_DEPTH, MAX_DEPTH);
        for (int i = tid; i < HW / 4; i += nth)
            ((float4*)g_depth)[i] = md4;

        float sx = 0.0f, sy = 0.0f, sz = 0.0f;
        float4 z4 = make_float4(0.0f, 0.0f, 0.0f, 0.0f);
        for (int i = tid; i < NV / 4; i += nth) {
            float4 a = verts4[3 * i + 0];   // v0.x v0.y v0.z v1.x
            float4 b = verts4[3 * i + 1];   // v1.y v1.z v2.x v2.y
            float4 c = verts4[3 * i + 2];   // v2.z v3.x v3.y v3.z
            float4 ra = vref4[3 * i + 0];
            float4 rb = vref4[3 * i + 1];
            float4 rc = vref4[3 * i + 2];
            sx += a.x + a.w + b.z + c.y;
            sy += a.y + b.x + b.w + c.z;
            sz += a.z + b.y + c.x + c.w;
            g_dv4[4 * i + 0] = make_float4(a.x - ra.x, a.y - ra.y, a.z - ra.z, 0.0f);
            g_dv4[4 * i + 1] = make_float4(a.w - ra.w, b.x - rb.x, b.y - rb.y, 0.0f);
            g_dv4[4 * i + 2] = make_float4(b.z - rb.z, b.w - rb.w, c.x - rc.x, 0.0f);
            g_dv4[4 * i + 3] = make_float4(c.y - rc.y, c.z - rc.z, c.w - rc.w, 0.0f);
            g_neigh4[4 * i + 0] = z4;
            g_neigh4[4 * i + 1] = z4;
            g_neigh4[4 * i + 2] = z4;
            g_neigh4[4 * i + 3] = z4;
        }
        float bx = block_reduce_f(sx);
        __syncthreads();
        float by = block_reduce_f(sy);
        __syncthreads();
        float bz = block_reduce_f(sz);
        if (threadIdx.x == 0) {
            atomicAdd(&g_sums[0], (double)bx);
            atomicAdd(&g_sums[1], (double)by);
            atomicAdd(&g_sums[2], (double)bz);
        }
    }
    grid.sync();

    // ===== Phase 2a: transform + project + scatter-min =====
    {
        float qx = quat[0], qy = quat[1], qz = quat[2], qw = quat[3];
        float qn = 1.0f / sqrtf(qx * qx + qy * qy + qz * qz + qw * qw);
        qx *= qn; qy *= qn; qz *= qn; qw *= qn;

        float mx = (float)(g_sums[0] / (double)NV);
        float my = (float)(g_sums[1] / (double)NV);
        float mz = (float)(g_sums[2] / (double)NV);

        float t0 = trans[0], t1 = trans[1], t2 = trans[2];
        float e0 = extr[0], e1 = extr[1], e2 = extr[2],  e3 = extr[3];
        float e4 = extr[4], e5 = extr[5], e6 = extr[6],  e7 = extr[7];
        float e8 = extr[8], e9 = extr[9], e10 = extr[10], e11 = extr[11];
        float i0 = intr[0], i1 = intr[1], i2 = intr[2];
        float i3 = intr[3], i4 = intr[4], i5 = intr[5];
        float i6 = intr[6], i7 = intr[7], i8 = intr[8];

        for (int i = tid; i < NV / 4; i += nth) {
            float4 a = verts4[3 * i + 0];
            float4 b = verts4[3 * i + 1];
            float4 c = verts4[3 * i + 2];
            float vxs[4] = {a.x, a.w, b.z, c.y};
            float vys[4] = {a.y, b.x, b.w, c.z};
            float vzs[4] = {a.z, b.y, c.x, c.w};

            #pragma unroll
            for (int k = 0; k < 4; k++) {
                float vx = vxs[k] - mx;
                float vy = vys[k] - my;
                float vz = vzs[k] - mz;

                float uvx = qy * vz - qz * vy;
                float uvy = qz * vx - qx * vz;
                float uvz = qx * vy - qy * vx;
                float uuvx = qy * uvz - qz * uvy;
                float uuvy = qz * uvx - qx * uvz;
                float uuvz = qx * uvy - qy * uvx;
                float tx = vx + 2.0f * (qw * uvx + uuvx) + t0;
                float ty = vy + 2.0f * (qw * uvy + uuvy) + t1;
                float tz = vz + 2.0f * (qw * uvz + uuvz) + t2;

                float p0 = e0 * tx + e1 * ty + e2  * tz + e3;
                float p1 = e4 * tx + e5 * ty + e6  * tz + e7;
                float p2 = e8 * tx + e9 * ty + e10 * tz + e11;

                float pr0 = i0 * p0 + i1 * p1 + i2 * p2;
                float pr1 = i3 * p0 + i4 * p1 + i5 * p2;
                float pr2 = i6 * p0 + i7 * p1 + i8 * p2;

                float u = pr0 / pr2;
                float v = pr1 / pr2;

                float fx = rintf(u);                  // round half to even
                float fy = rintf(v);
                fx = fminf(fmaxf(fx, 0.0f), (float)(IMG_W - 1));
                fy = fminf(fmaxf(fy, 0.0f), (float)(IMG_H - 1));
                int flat = (int)fy * IMG_W + (int)fx;

                float zval = (p2 > 0.0f) ? p2 : MAX_DEPTH;   // DEPTH_SCALE = 1
                // zval > 0, so int-bitpattern min == float min
                atomicMin((int*)&g_depth[flat], __float_as_int(zval));
            }
        }
    }

    // ===== Phase 2b: edge accumulation (needs phase-1 dv/neigh only) =====
    for (int e = tid; e < NE / 2; e += nth) {
        int4 p = edges2[e];                   // (s0, d0, s1, d1)
        float4 dv0 = g_dv4[p.y];
        float4 dv1 = g_dv4[p.w];
        asm volatile(
            "red.global.add.v4.f32 [%0], {%1, %2, %3, %4};"
            :: "l"(&g_neigh4[p.x]), "f"(dv0.x), "f"(dv0.y), "f"(dv0.z), "f"(1.0f)
            : "memory");
        asm volatile(
            "red.global.add.v4.f32 [%0], {%1, %2, %3, %4};"
            :: "l"(&g_neigh4[p.z]), "f"(dv1.x), "f"(dv1.y), "f"(dv1.z), "f"(1.0f)
            : "memory");
    }
    grid.sync();

    // ===== Phase 3: energy (data + rigid) =====
    {
        float local = 0.0f;
        for (int i = tid; i < HW / 4; i += nth) {
            float4 d = ((const float4*)g_depth)[i];
            float4 h = hand4[i];
            float d0 = d.x - h.x, d1 = d.y - h.y, d2 = d.z - h.z, d3 = d.w - h.w;
            local += d0 * d0 + d1 * d1 + d2 * d2 + d3 * d3;
        }
        for (int i = tid; i < NV; i += nth) {
            float4 dv = g_dv4[i];
            float4 nb = g_neigh4[i];
            float dg = nb.w;
            float lx = dg * dv.x - nb.x;
            float ly = dg * dv.y - nb.y;
            float lz = dg * dv.z - nb.z;
            local += CREGU * (lx * lx + ly * ly + lz * lz);
        }
        float b = block_reduce_f(local);
        if (threadIdx.x == 0) atomicAdd(&g_acc, (double)b);
    }
    grid.sync();

    // ===== finalize + re-zero for next replay =====
    if (tid == 0) {
        out[0] = (float)g_acc;
        g_acc = 0.0;
        g_sums[0] = 0.0; g_sums[1] = 0.0; g_sums[2] = 0.0;
    }
}

// ---------------- fallback (proven 5-kernel path) ----------------------------
__global__ void k_mean_fill(const float4* __restrict__ verts4,
                            const float4* __restrict__ vref4) {
    int i = blockIdx.x * blockDim.x + threadIdx.x;
    ((float4*)g_depth)[i] = make_float4(MAX_DEPTH, MAX_DEPTH, MAX_DEPTH, MAX_DEPTH);
    float sx = 0.0f, sy = 0.0f, sz = 0.0f;
    if (i < NV / 4) {
        float4 a = verts4[3 * i + 0];
        float4 b = verts4[3 * i + 1];
        float4 c = verts4[3 * i + 2];
        float4 ra = vref4[3 * i + 0];
        float4 rb = vref4[3 * i + 1];
        float4 rc = vref4[3 * i + 2];
        sx = a.x + a.w + b.z + c.y;
        sy = a.y + b.x + b.w + c.z;
        sz = a.z + b.y + c.x + c.w;
        g_dv4[4 * i + 0] = make_float4(a.x - ra.x, a.y - ra.y, a.z - ra.z, 0.0f);
        g_dv4[4 * i + 1] = make_float4(a.w - ra.w, b.x - rb.x, b.y - rb.y, 0.0f);
        g_dv4[4 * i + 2] = make_float4(b.z - rb.z, b.w - rb.w, c.x - rc.x, 0.0f);
        g_dv4[4 * i + 3] = make_float4(c.y - rc.y, c.z - rc.z, c.w - rc.w, 0.0f);
        float4 z4 = make_float4(0.0f, 0.0f, 0.0f, 0.0f);
        g_neigh4[4 * i + 0] = z4;
        g_neigh4[4 * i + 1] = z4;
        g_neigh4[4 * i + 2] = z4;
        g_neigh4[4 * i + 3] = z4;
    }
    float bx = block_reduce_f(sx);
    __syncthreads();
    float by = block_reduce_f(sy);
    __syncthreads();
    float bz = block_reduce_f(sz);
    if (threadIdx.x == 0) {
        atomicAdd(&g_sums[0], (double)bx);
        atomicAdd(&g_sums[1], (double)by);
        atomicAdd(&g_sums[2], (double)bz);
    }
}

__global__ void k_proj(const float4* __restrict__ verts4,
                       const float* __restrict__ quat,
                       const float* __restrict__ trans,
                       const float* __restrict__ intr,
                       const float* __restrict__ extr) {
    int i = blockIdx.x * blockDim.x + threadIdx.x;
    if (i >= NV / 4) return;
    float qx = quat[0], qy = quat[1], qz = quat[2], qw = quat[3];
    float qn = 1.0f / sqrtf(qx * qx + qy * qy + qz * qz + qw * qw);
    qx *= qn; qy *= qn; qz *= qn; qw *= qn;
    float mx = (float)(g_sums[0] / (double)NV);
    float my = (float)(g_sums[1] / (double)NV);
    float mz = (float)(g_sums[2] / (double)NV);
    float4 a = verts4[3 * i + 0];
    float4 b = verts4[3 * i + 1];
    float4 c = verts4[3 * i + 2];
    float vxs[4] = {a.x, a.w, b.z, c.y};
    float vys[4] = {a.y, b.x, b.w, c.z};
    float vzs[4] = {a.z, b.y, c.x, c.w};
    #pragma unroll
    for (int k = 0; k < 4; k++) {
        float vx = vxs[k] - mx, vy = vys[k] - my, vz = vzs[k] - mz;
        float uvx = qy * vz - qz * vy;
        float uvy = qz * vx - qx * vz;
        float uvz = qx * vy - qy * vx;
        float uuvx = qy * uvz - qz * uvy;
        float uuvy = qz * uvx - qx * uvz;
        float uuvz = qx * uvy - qy * uvx;
        float tx = vx + 2.0f * (qw * uvx + uuvx) + trans[0];
        float ty = vy + 2.0f * (qw * uvy + uuvy) + trans[1];
        float tz = vz + 2.0f * (qw * uvz + uuvz) + trans[2];
        float p0 = extr[0] * tx + extr[1] * ty + extr[2]  * tz + extr[3];
        float p1 = extr[4] * tx + extr[5] * ty + extr[6]  * tz + extr[7];
        float p2 = extr[8] * tx + extr[9] * ty + extr[10] * tz + extr[11];
        float pr0 = intr[0] * p0 + intr[1] * p1 + intr[2] * p2;
        float pr1 = intr[3] * p0 + intr[4] * p1 + intr[5] * p2;
        float pr2 = intr[6] * p0 + intr[7] * p1 + intr[8] * p2;
        float u = pr0 / pr2, v = pr1 / pr2;
        float fx = rintf(u), fy = rintf(v);
        fx = fminf(fmaxf(fx, 0.0f), (float)(IMG_W - 1));
        fy = fminf(fmaxf(fy, 0.0f), (float)(IMG_H - 1));
        int flat = (int)fy * IMG_W + (int)fx;
        float zval = (p2 > 0.0f) ? p2 : MAX_DEPTH;
        atomicMin((int*)&g_depth[flat], __float_as_int(zval));
    }
}

__global__ void k_edge(const int4* __restrict__ edges2) {
    int e = blockIdx.x * blockDim.x + threadIdx.x;
    if (e >= NE / 2) return;
    int4 p = edges2[e];
    float4 dv0 = g_dv4[p.y];
    float4 dv1 = g_dv4[p.w];
    asm volatile("red.global.add.v4.f32 [%0], {%1, %2, %3, %4};"
        :: "l"(&g_neigh4[p.x]), "f"(dv0.x), "f"(dv0.y), "f"(dv0.z), "f"(1.0f) : "memory");
    asm volatile("red.global.add.v4.f32 [%0], {%1, %2, %3, %4};"
        :: "l"(&g_neigh4[p.z]), "f"(dv1.x), "f"(dv1.y), "f"(dv1.z), "f"(1.0f) : "memory");
}

__global__ void k_energy(const float4* __restrict__ hand4) {
    int i = blockIdx.x * blockDim.x + threadIdx.x;
    float local = 0.0f;
    float4 d = ((const float4*)g_depth)[i];
    float4 h = hand4[i];
    float d0 = d.x - h.x, d1 = d.y - h.y, d2 = d.z - h.z, d3 = d.w - h.w;
    local = d0 * d0 + d1 * d1 + d2 * d2 + d3 * d3;
    if (i < NV / 4) {
        #pragma unroll
        for (int k = 0; k < 4; k++) {
            float4 dv = g_dv4[4 * i + k];
            float4 nb = g_neigh4[4 * i + k];
            float dg = nb.w;
            float lx = dg * dv.x - nb.x;
            float ly = dg * dv.y - nb.y;
            float lz = dg * dv.z - nb.z;
            local += CREGU * (lx * lx + ly * ly + lz * lz);
        }
    }
    float b = block_reduce_f(local);
    if (threadIdx.x == 0) atomicAdd(&g_acc, (double)b);
}

__global__ void k_final(float* __restrict__ out) {
    out[0] = (float)g_acc;
    g_acc = 0.0;
    g_sums[0] = 0.0; g_sums[1] = 0.0; g_sums[2] = 0.0;
}

// ---------------- launch -----------------------------------------------------
extern "C" void kernel_launch(void* const* d_in, const int* in_sizes, int n_in,
                              void* d_out, int out_size) {
    const float4* verts4 = (const float4*)d_in[0];
    const float4* vref4  = (const float4*)d_in[1];
    const float*  quat   = (const float*)d_in[2];
    const float*  trans  = (const float*)d_in[3];
    const float4* hand4  = (const float4*)d_in[4];
    const float*  intr   = (const float*)d_in[5];
    const float*  extr   = (const float*)d_in[6];
    const int4*   edges2 = (const int4*)d_in[7];
    float* out = (float*)d_out;

    const int B = 256;

    int dev = 0, coop = 0, sms = 0;
    cudaGetDevice(&dev);
    cudaDeviceGetAttribute(&coop, cudaDevAttrCooperativeLaunch, dev);
    cudaDeviceGetAttribute(&sms, cudaDevAttrMultiProcessorCount, dev);
    int maxb = 0;
    cudaOccupancyMaxActiveBlocksPerMultiprocessor(&maxb, k_fused, B, 0);

    if (coop && maxb > 0) {
        int grid = sms * maxb;
        if (grid > 4096) grid = 4096;
        void* args[] = {(void*)&verts4, (void*)&vref4, (void*)&quat,
                        (void*)&trans,  (void*)&hand4, (void*)&intr,
                        (void*)&extr,   (void*)&edges2, (void*)&out};
        cudaLaunchCooperativeKernel((void*)k_fused, dim3(grid), dim3(B),
                                    args, 0, 0);
    } else {
        k_mean_fill<<<(HW / 4) / B, B>>>(verts4, vref4);
        k_proj<<<(NV / 4 + B - 1) / B, B>>>(verts4, quat, trans, intr, extr);
        k_edge<<<(NE / 2 + B - 1) / B, B>>>(edges2);
        k_energy<<<(HW / 4) / B, B>>>(hand4);
        k_final<<<1, 1>>>(out);
    }
}

// round 9
// speedup vs baseline: 1.1011x; 1.1011x over previous
#include <cuda_runtime.h>
#include <cuda_bf16.h>
#include <cstdint>

// Problem constants (match reference_code)
#define NV       1000000
#define NE       3000000
#define IMG_H    1024
#define IMG_W    1024
#define HW       (IMG_H * IMG_W)       // 1048576
#define MAX_DEPTH 10.0f
#define CREGU    2000.0f

#define B        256
#define PROJ_BLOCKS  ((NV / 4 + B - 1) / B)   // 977
#define EDGE_BLOCKS  ((NE / 2 + B - 1) / B)   // 5860

// ---------------- scratch (device globals; zero-initialized at load) --------
__device__ float    g_depth[HW];      // 4 MB    scatter-min target
__device__ float4   g_dv4[NV];        // 16 MB   {dvx, dvy, dvz, 0}
__device__ float4   g_neigh4[NV];     // 16 MB   {nx, ny, nz, deg}
__device__ double   g_sums[3];        // vertex component sums (self-zeroing)
__device__ double   g_acc;            // total energy accumulator (self-zeroing)
__device__ unsigned g_done;           // last-block counter (self-zeroing)

// ---------------- float block reduce (shared) --------------------------------
__device__ __forceinline__ float block_reduce_f(float v) {
    __shared__ float sh[B];
    int t = threadIdx.x;
    sh[t] = v;
    __syncthreads();
    for (int s = blockDim.x >> 1; s > 32; s >>= 1) {
        if (t < s) sh[t] += sh[t + s];
        __syncthreads();
    }
    if (t < 32) {
        float x = sh[t] + sh[t + 32];
        #pragma unroll
        for (int o = 16; o > 0; o >>= 1)
            x += __shfl_down_sync(0xFFFFFFFFu, x, o);
        if (t == 0) sh[0] = x;
    }
    __syncthreads();
    return sh[0];
}

// ---------------- K1: depth fill + neigh zero + dv + mean partials -----------
// 262144 threads: 4 depth pixels each; threads < 250000 also handle 4 verts.
__global__ void k_mean_fill(const float4* __restrict__ verts4,
                            const float4* __restrict__ vref4) {
    int i = blockIdx.x * blockDim.x + threadIdx.x;
    ((float4*)g_depth)[i] = make_float4(MAX_DEPTH, MAX_DEPTH, MAX_DEPTH, MAX_DEPTH);

    float sx = 0.0f, sy = 0.0f, sz = 0.0f;
    if (i < NV / 4) {
        float4 a = verts4[3 * i + 0];   // v0.x v0.y v0.z v1.x
        float4 b = verts4[3 * i + 1];   // v1.y v1.z v2.x v2.y
        float4 c = verts4[3 * i + 2];   // v2.z v3.x v3.y v3.z
        float4 ra = vref4[3 * i + 0];
        float4 rb = vref4[3 * i + 1];
        float4 rc = vref4[3 * i + 2];
        sx = a.x + a.w + b.z + c.y;
        sy = a.y + b.x + b.w + c.z;
        sz = a.z + b.y + c.x + c.w;
        g_dv4[4 * i + 0] = make_float4(a.x - ra.x, a.y - ra.y, a.z - ra.z, 0.0f);
        g_dv4[4 * i + 1] = make_float4(a.w - ra.w, b.x - rb.x, b.y - rb.y, 0.0f);
        g_dv4[4 * i + 2] = make_float4(b.z - rb.z, b.w - rb.w, c.x - rc.x, 0.0f);
        g_dv4[4 * i + 3] = make_float4(c.y - rc.y, c.z - rc.z, c.w - rc.w, 0.0f);
        float4 z4 = make_float4(0.0f, 0.0f, 0.0f, 0.0f);
        g_neigh4[4 * i + 0] = z4;
        g_neigh4[4 * i + 1] = z4;
        g_neigh4[4 * i + 2] = z4;
        g_neigh4[4 * i + 3] = z4;
    }
    float bx = block_reduce_f(sx);
    __syncthreads();
    float by = block_reduce_f(sy);
    __syncthreads();
    float bz = block_reduce_f(sz);
    if (threadIdx.x == 0) {
        atomicAdd(&g_sums[0], (double)bx);
        atomicAdd(&g_sums[1], (double)by);
        atomicAdd(&g_sums[2], (double)bz);
    }
}

// ---------------- K2: heterogeneous proj + edge (both depend only on K1) ----
// Blocks [0, PROJ_BLOCKS): transform+project+scatter-min (4 verts/thread).
// Blocks [PROJ_BLOCKS, PROJ_BLOCKS+EDGE_BLOCKS): edge accumulation (2/thread).
__global__ void k_proj_edge(const float4* __restrict__ verts4,
                            const float* __restrict__ quat,
                            const float* __restrict__ trans,
                            const float* __restrict__ intr,
                            const float* __restrict__ extr,
                            const int4* __restrict__ edges2) {
    if (blockIdx.x < PROJ_BLOCKS) {
        int i = blockIdx.x * blockDim.x + threadIdx.x;
        if (i >= NV / 4) return;

        float qx = quat[0], qy = quat[1], qz = quat[2], qw = quat[3];
        float qn = 1.0f / sqrtf(qx * qx + qy * qy + qz * qz + qw * qw);
        qx *= qn; qy *= qn; qz *= qn; qw *= qn;

        float mx = (float)(g_sums[0] / (double)NV);
        float my = (float)(g_sums[1] / (double)NV);
        float mz = (float)(g_sums[2] / (double)NV);

        float4 a = verts4[3 * i + 0];
        float4 b = verts4[3 * i + 1];
        float4 c = verts4[3 * i + 2];
        float vxs[4] = {a.x, a.w, b.z, c.y};
        float vys[4] = {a.y, b.x, b.w, c.z};
        float vzs[4] = {a.z, b.y, c.x, c.w};

        #pragma unroll
        for (int k = 0; k < 4; k++) {
            float vx = vxs[k] - mx;
            float vy = vys[k] - my;
            float vz = vzs[k] - mz;

            // qrot: v + 2*(w*uv + uuv), uv = qv x v, uuv = qv x uv
            float uvx = qy * vz - qz * vy;
            float uvy = qz * vx - qx * vz;
            float uvz = qx * vy - qy * vx;
            float uuvx = qy * uvz - qz * uvy;
            float uuvy = qz * uvx - qx * uvz;
            float uuvz = qx * uvy - qy * uvx;
            float tx = vx + 2.0f * (qw * uvx + uuvx) + trans[0];
            float ty = vy + 2.0f * (qw * uvy + uuvy) + trans[1];
            float tz = vz + 2.0f * (qw * uvz + uuvz) + trans[2];

            // p_cam = E[:, :3] @ v_t + E[:, 3]   (extr row-major 3x4)
            float p0 = extr[0] * tx + extr[1] * ty + extr[2]  * tz + extr[3];
            float p1 = extr[4] * tx + extr[5] * ty + extr[6]  * tz + extr[7];
            float p2 = extr[8] * tx + extr[9] * ty + extr[10] * tz + extr[11];

            // proj = K @ p_cam (intr row-major 3x3)
            float pr0 = intr[0] * p0 + intr[1] * p1 + intr[2] * p2;
            float pr1 = intr[3] * p0 + intr[4] * p1 + intr[5] * p2;
            float pr2 = intr[6] * p0 + intr[7] * p1 + intr[8] * p2;

            float u = pr0 / pr2;
            float v = pr1 / pr2;

            float fx = rintf(u);                  // round half to even
            float fy = rintf(v);
            fx = fminf(fmaxf(fx, 0.0f), (float)(IMG_W - 1));
            fy = fminf(fmaxf(fy, 0.0f), (float)(IMG_H - 1));
            int flat = (int)fy * IMG_W + (int)fx;

            float zval = (p2 > 0.0f) ? p2 : MAX_DEPTH;   // DEPTH_SCALE = 1
            // zval > 0, so int-bitpattern min == float min
            atomicMin((int*)&g_depth[flat], __float_as_int(zval));
        }
    } else {
        int e = (blockIdx.x - PROJ_BLOCKS) * blockDim.x + threadIdx.x;
        if (e >= NE / 2) return;
        int4 p = edges2[e];                   // (s0, d0, s1, d1), 16B coalesced
        float4 dv0 = g_dv4[p.y];
        float4 dv1 = g_dv4[p.w];
        asm volatile(
            "red.global.add.v4.f32 [%0], {%1, %2, %3, %4};"
            :: "l"(&g_neigh4[p.x]), "f"(dv0.x), "f"(dv0.y), "f"(dv0.z), "f"(1.0f)
            : "memory");
        asm volatile(
            "red.global.add.v4.f32 [%0], {%1, %2, %3, %4};"
            :: "l"(&g_neigh4[p.z]), "f"(dv1.x), "f"(dv1.y), "f"(dv1.z), "f"(1.0f)
            : "memory");
    }
}

// ---------------- K3: energy + last-block finalize ---------------------------
__global__ void k_energy_final(const float4* __restrict__ hand4,
                               float* __restrict__ out) {
    int i = blockIdx.x * blockDim.x + threadIdx.x;   // < 262144
    float local = 0.0f;

    float4 d = ((const float4*)g_depth)[i];
    float4 h = hand4[i];
    float d0 = d.x - h.x, d1 = d.y - h.y, d2 = d.z - h.z, d3 = d.w - h.w;
    local = d0 * d0 + d1 * d1 + d2 * d2 + d3 * d3;

    if (i < NV / 4) {
        #pragma unroll
        for (int k = 0; k < 4; k++) {
            float4 dv = g_dv4[4 * i + k];
            float4 nb = g_neigh4[4 * i + k];
            float dg = nb.w;
            float lx = dg * dv.x - nb.x;
            float ly = dg * dv.y - nb.y;
            float lz = dg * dv.z - nb.z;
            local += CREGU * (lx * lx + ly * ly + lz * lz);
        }
    }
    float b = block_reduce_f(local);
    if (threadIdx.x == 0) {
        atomicAdd(&g_acc, (double)b);
        __threadfence();
        unsigned t = atomicAdd(&g_done, 1u);
        if (t == gridDim.x - 1) {      // last block: finalize + re-zero
            out[0] = (float)g_acc;
            g_acc = 0.0;
            g_sums[0] = 0.0; g_sums[1] = 0.0; g_sums[2] = 0.0;
            g_done = 0u;
        }
    }
}

// ---------------- launch -----------------------------------------------------
extern "C" void kernel_launch(void* const* d_in, const int* in_sizes, int n_in,
                              void* d_out, int out_size) {
    const float4* verts4 = (const float4*)d_in[0];
    const float4* vref4  = (const float4*)d_in[1];
    const float*  quat   = (const float*)d_in[2];
    const float*  trans  = (const float*)d_in[3];
    const float4* hand4  = (const float4*)d_in[4];
    const float*  intr   = (const float*)d_in[5];
    const float*  extr   = (const float*)d_in[6];
    const int4*   edges2 = (const int4*)d_in[7];
    float* out = (float*)d_out;

    k_mean_fill<<<(HW / 4) / B, B>>>(verts4, vref4);              // 1024 blocks
    k_proj_edge<<<PROJ_BLOCKS + EDGE_BLOCKS, B>>>(verts4, quat, trans,
                                                  intr, extr, edges2);
    k_energy_final<<<(HW / 4) / B, B>>>(hand4, out);
}

// round 11
// speedup vs baseline: 1.1811x; 1.0726x over previous
#include <cuda_runtime.h>
#include <cuda_bf16.h>
#include <cstdint>

// Problem constants (match reference_code)
#define NV       1000000
#define NE       3000000
#define IMG_H    1024
#define IMG_W    1024
#define HW       (IMG_H * IMG_W)       // 1048576
#define MAX_DEPTH 10.0f
#define CREGU    2000.0f

#define B        256
#define NQ       (NV / 4)                      // 250000 vertex quads
#define PRE_BLOCKS   ((HW / 4) / B)            // 1024
#define PROJ_BLOCKS  ((NQ + B - 1) / B)        // 977
#define EDGE_BLOCKS  ((NE / 2 + B - 1) / B)    // 5860

// ---------------- scratch (device globals; zero-initialized at load) --------
__device__ float    g_depth[HW];      // 4 MB    scatter-min target
__device__ float4   g_dv4[NV];        // 16 MB   {dvx, dvy, dvz, 0}
__device__ float4   g_neigh4[NV];     // 16 MB   {nx, ny, nz, deg}
__device__ double   g_sums[3];        // vertex component sums (self-zeroing)
__device__ double   g_acc;            // total energy accumulator (self-zeroing)
__device__ unsigned g_done;           // last-block counter (self-zeroing)

// ---------------- float block reduce (shared) --------------------------------
__device__ __forceinline__ float block_reduce_f(float v) {
    __shared__ float sh[B];
    int t = threadIdx.x;
    sh[t] = v;
    __syncthreads();
    for (int s = blockDim.x >> 1; s > 32; s >>= 1) {
        if (t < s) sh[t] += sh[t + s];
        __syncthreads();
    }
    if (t < 32) {
        float x = sh[t] + sh[t + 32];
        #pragma unroll
        for (int o = 16; o > 0; o >>= 1)
            x += __shfl_down_sync(0xFFFFFFFFu, x, o);
        if (t == 0) sh[0] = x;
    }
    __syncthreads();
    return sh[0];
}

// ---------------- K1: depth fill + vertex mean partials ----------------------
// MUST complete before any atomicMin on g_depth (separate launch = ordered).
__global__ void k_mean_fill(const float4* __restrict__ verts4) {
    int i = blockIdx.x * blockDim.x + threadIdx.x;   // < 262144
    ((float4*)g_depth)[i] = make_float4(MAX_DEPTH, MAX_DEPTH, MAX_DEPTH, MAX_DEPTH);

    float sx = 0.0f, sy = 0.0f, sz = 0.0f;
    if (i < NQ) {
        float4 a = verts4[3 * i + 0];   // v0.x v0.y v0.z v1.x
        float4 b = verts4[3 * i + 1];   // v1.y v1.z v2.x v2.y
        float4 c = verts4[3 * i + 2];   // v2.z v3.x v3.y v3.z
        sx = a.x + a.w + b.z + c.y;
        sy = a.y + b.x + b.w + c.z;
        sz = a.z + b.y + c.x + c.w;
    }
    float bx = block_reduce_f(sx);
    __syncthreads();
    float by = block_reduce_f(sy);
    __syncthreads();
    float bz = block_reduce_f(sz);
    if (threadIdx.x == 0) {
        atomicAdd(&g_sums[0], (double)bx);
        atomicAdd(&g_sums[1], (double)by);
        atomicAdd(&g_sums[2], (double)bz);
    }
}

// ---------------- K2: dv + neigh zero + project (verts read once) ------------
__global__ void k_pre_proj(const float4* __restrict__ verts4,
                           const float4* __restrict__ vref4,
                           const float* __restrict__ quat,
                           const float* __restrict__ trans,
                           const float* __restrict__ intr,
                           const float* __restrict__ extr) {
    int i = blockIdx.x * blockDim.x + threadIdx.x;   // < 250000
    if (i >= NQ) return;

    float4 a = verts4[3 * i + 0];
    float4 b = verts4[3 * i + 1];
    float4 c = verts4[3 * i + 2];
    float4 ra = vref4[3 * i + 0];
    float4 rb = vref4[3 * i + 1];
    float4 rc = vref4[3 * i + 2];

    g_dv4[4 * i + 0] = make_float4(a.x - ra.x, a.y - ra.y, a.z - ra.z, 0.0f);
    g_dv4[4 * i + 1] = make_float4(a.w - ra.w, b.x - rb.x, b.y - rb.y, 0.0f);
    g_dv4[4 * i + 2] = make_float4(b.z - rb.z, b.w - rb.w, c.x - rc.x, 0.0f);
    g_dv4[4 * i + 3] = make_float4(c.y - rc.y, c.z - rc.z, c.w - rc.w, 0.0f);
    float4 z4 = make_float4(0.0f, 0.0f, 0.0f, 0.0f);
    g_neigh4[4 * i + 0] = z4;
    g_neigh4[4 * i + 1] = z4;
    g_neigh4[4 * i + 2] = z4;
    g_neigh4[4 * i + 3] = z4;

    // ---- projection (mean ready from K1; depth filled by K1) ----
    float qx = quat[0], qy = quat[1], qz = quat[2], qw = quat[3];
    float qn = 1.0f / sqrtf(qx * qx + qy * qy + qz * qz + qw * qw);
    qx *= qn; qy *= qn; qz *= qn; qw *= qn;

    float mx = (float)(g_sums[0] / (double)NV);
    float my = (float)(g_sums[1] / (double)NV);
    float mz = (float)(g_sums[2] / (double)NV);

    float vxs[4] = {a.x, a.w, b.z, c.y};
    float vys[4] = {a.y, b.x, b.w, c.z};
    float vzs[4] = {a.z, b.y, c.x, c.w};

    #pragma unroll
    for (int k = 0; k < 4; k++) {
        float vx = vxs[k] - mx;
        float vy = vys[k] - my;
        float vz = vzs[k] - mz;

        // qrot: v + 2*(w*uv + uuv), uv = qv x v, uuv = qv x uv
        float uvx = qy * vz - qz * vy;
        float uvy = qz * vx - qx * vz;
        float uvz = qx * vy - qy * vx;
        float uuvx = qy * uvz - qz * uvy;
        float uuvy = qz * uvx - qx * uvz;
        float uuvz = qx * uvy - qy * uvx;
        float tx = vx + 2.0f * (qw * uvx + uuvx) + trans[0];
        float ty = vy + 2.0f * (qw * uvy + uuvy) + trans[1];
        float tz = vz + 2.0f * (qw * uvz + uuvz) + trans[2];

        // p_cam = E[:, :3] @ v_t + E[:, 3]   (extr row-major 3x4)
        float p0 = extr[0] * tx + extr[1] * ty + extr[2]  * tz + extr[3];
        float p1 = extr[4] * tx + extr[5] * ty + extr[6]  * tz + extr[7];
        float p2 = extr[8] * tx + extr[9] * ty + extr[10] * tz + extr[11];

        // proj = K @ p_cam (intr row-major 3x3)
        float pr0 = intr[0] * p0 + intr[1] * p1 + intr[2] * p2;
        float pr1 = intr[3] * p0 + intr[4] * p1 + intr[5] * p2;
        float pr2 = intr[6] * p0 + intr[7] * p1 + intr[8] * p2;

        float u = pr0 / pr2;
        float v = pr1 / pr2;

        float fx = rintf(u);                  // round half to even == jnp.round
        float fy = rintf(v);
        fx = fminf(fmaxf(fx, 0.0f), (float)(IMG_W - 1));
        fy = fminf(fmaxf(fy, 0.0f), (float)(IMG_H - 1));
        int flat = (int)fy * IMG_W + (int)fx;

        float zval = (p2 > 0.0f) ? p2 : MAX_DEPTH;   // DEPTH_SCALE = 1
        // zval > 0, so int-bitpattern min == float min
        atomicMin((int*)&g_depth[flat], __float_as_int(zval));
    }
}

// ---------------- K3: edge accumulation (2 edges/thread, v4 reductions) -----
__global__ void k_edge(const int4* __restrict__ edges2) {
    int e = blockIdx.x * blockDim.x + threadIdx.x;   // < NE/2
    if (e >= NE / 2) return;
    int4 p = edges2[e];                   // (s0, d0, s1, d1), 16B coalesced
    float4 dv0 = g_dv4[p.y];
    float4 dv1 = g_dv4[p.w];
    asm volatile(
        "red.global.add.v4.f32 [%0], {%1, %2, %3, %4};"
        :: "l"(&g_neigh4[p.x]), "f"(dv0.x), "f"(dv0.y), "f"(dv0.z), "f"(1.0f)
        : "memory");
    asm volatile(
        "red.global.add.v4.f32 [%0], {%1, %2, %3, %4};"
        :: "l"(&g_neigh4[p.z]), "f"(dv1.x), "f"(dv1.y), "f"(dv1.z), "f"(1.0f)
        : "memory");
}

// ---------------- K4: energy + last-block finalize ---------------------------
__global__ void k_energy_final(const float4* __restrict__ hand4,
                               float* __restrict__ out) {
    int i = blockIdx.x * blockDim.x + threadIdx.x;   // < 262144
    float local = 0.0f;

    float4 d = ((const float4*)g_depth)[i];
    float4 h = hand4[i];
    float d0 = d.x - h.x, d1 = d.y - h.y, d2 = d.z - h.z, d3 = d.w - h.w;
    local = d0 * d0 + d1 * d1 + d2 * d2 + d3 * d3;

    if (i < NQ) {
        #pragma unroll
        for (int k = 0; k < 4; k++) {
            float4 dv = g_dv4[4 * i + k];
            float4 nb = g_neigh4[4 * i + k];
            float dg = nb.w;
            float lx = dg * dv.x - nb.x;
            float ly = dg * dv.y - nb.y;
            float lz = dg * dv.z - nb.z;
            local += CREGU * (lx * lx + ly * ly + lz * lz);
        }
    }
    float b = block_reduce_f(local);
    if (threadIdx.x == 0) {
        atomicAdd(&g_acc, (double)b);
        __threadfence();
        unsigned t = atomicAdd(&g_done, 1u);
        if (t == gridDim.x - 1) {      // last block: finalize + re-zero
            out[0] = (float)g_acc;
            g_acc = 0.0;
            g_sums[0] = 0.0; g_sums[1] = 0.0; g_sums[2] = 0.0;
            g_done = 0u;
        }
    }
}

// ---------------- launch -----------------------------------------------------
extern "C" void kernel_launch(void* const* d_in, const int* in_sizes, int n_in,
                              void* d_out, int out_size) {
    const float4* verts4 = (const float4*)d_in[0];
    const float4* vref4  = (const float4*)d_in[1];
    const float*  quat   = (const float*)d_in[2];
    const float*  trans  = (const float*)d_in[3];
    const float4* hand4  = (const float4*)d_in[4];
    const float*  intr   = (const float*)d_in[5];
    const float*  extr   = (const float*)d_in[6];
    const int4*   edges2 = (const int4*)d_in[7];
    float* out = (float*)d_out;

    k_mean_fill<<<PRE_BLOCKS, B>>>(verts4);
    k_pre_proj<<<PROJ_BLOCKS, B>>>(verts4, vref4, quat, trans, intr, extr);
    k_edge<<<EDGE_BLOCKS, B>>>(edges2);
    k_energy_final<<<PRE_BLOCKS, B>>>(hand4, out);
}